// round 11
// baseline (speedup 1.0000x reference)
#include <cuda_runtime.h>
#include <math.h>

#define CHN 143
#define NT  128

// Packed weights (float4 per (cout,cin) triple, 4th lane = 0).
// Layout (float4 units): W1@0(32), W2@32(448), W3@480(784), W4@1264(784),
//                        F1@2048(8), F2@2056(16), F3@2072(16), F4@2088(16)
__device__   float4 g_Wp_stage[2104];   // staging, written by init_pack
__constant__ float4 c_Wp[2104];         // published via cudaMemcpyToSymbolAsync
__device__   float2 g_tw[144];          // twiddles stay in global (smem-loaded, divergent index)

__device__ __forceinline__ void copy3(float* dst, const float* src) {
    dst[0] = src[0]; dst[1] = src[1]; dst[2] = src[2]; dst[3] = 0.f;
}

__global__ void init_pack(const float* w1, const float* w2, const float* w3, const float* w4,
                          const float* f1, const float* f2, const float* f3, const float* f4)
{
    int tid = threadIdx.x;
    float* g = (float*)g_Wp_stage;
    for (int e = tid; e < 32;  e += 256) copy3(g + (0    + e) * 4, w1 + e * 3);
    for (int e = tid; e < 448; e += 256) copy3(g + (32   + e) * 4, w2 + e * 3);
    for (int e = tid; e < 784; e += 256) copy3(g + (480  + e) * 4, w3 + e * 3);
    for (int e = tid; e < 784; e += 256) copy3(g + (1264 + e) * 4, w4 + e * 3);
    for (int e = tid; e < 8;   e += 256) copy3(g + (2048 + e) * 4, f1 + e * 3);
    for (int e = tid; e < 16;  e += 256) copy3(g + (2056 + e) * 4, f2 + e * 3);
    for (int e = tid; e < 16;  e += 256) copy3(g + (2072 + e) * 4, f3 + e * 3);
    for (int e = tid; e < 16;  e += 256) copy3(g + (2088 + e) * 4, f4 + e * 3);
    if (tid < 143) {
        double a = -2.0 * 3.14159265358979323846 * (double)tid / 143.0;
        g_tw[tid] = make_float2((float)cos(a), (float)sin(a));
    }
}

// One DFT bin task: u in [0,144) -> (vector c, bin k). Writes |X[k]| and |X[143-k]|.
__device__ __forceinline__ void dft_one(int u, const float* raw, const float2* twl, float* vin)
{
    int c = (u >= 72) ? 1 : 0;
    int k = u - 72 * c;
    const float* v = raw + c * 144;
    float re = 0.f, im = 0.f;
    unsigned mc = 0;
#pragma unroll 13
    for (int n = 0; n < 143; n++) {
        float2 w = twl[mc];
        float val = v[n];
        re = fmaf(w.x, val, re);
        im = fmaf(w.y, val, im);
        mc += (unsigned)k;
        mc = min(mc, mc - 143u);   // conditional wrap via unsigned-min trick
    }
    float mag = sqrtf(fmaf(re, re, im * im));
    vin[c * 144 + k] = mag;
    if (k) vin[c * 144 + 143 - k] = mag;
}

// Conv1d(k=3, stride 2, VALID) + LayerNorm(last axis) + ReLU.
// Warp w handles rows c = w, w+4, ...; lane handles positions l = lane + 32*i.
// Weights come from __constant__ c_Wp at integer offset wbase: warp-uniform
// indices -> LDCU on the uniform/constant port, no L1tex wavefronts.
template<int Cin, int Cout, int Sin, int Lout, int NI>
__device__ __forceinline__ void convBlock(
    const float* __restrict__ in, float* __restrict__ out, int Sout,
    int wbase,
    const float* __restrict__ gam, const float* __restrict__ bet,
    int warp, int lane)
{
    constexpr int ROWS = Cout / 4;
    float acc[ROWS][NI];
#pragma unroll
    for (int r = 0; r < ROWS; r++)
#pragma unroll
        for (int i = 0; i < NI; i++) acc[r][i] = 0.f;

#pragma unroll 4
    for (int ic = 0; ic < Cin; ic++) {
        const float* row = in + ic * Sin;
        float x0[NI], x1[NI], x2[NI];
#pragma unroll
        for (int i = 0; i < NI; i++) {
            int l = lane + 32 * i;
            if (l < Lout) {
                float2 p = *(const float2*)(row + 2 * l);
                x0[i] = p.x; x1[i] = p.y; x2[i] = row[2 * l + 2];
            } else { x0[i] = 0.f; x1[i] = 0.f; x2[i] = 0.f; }
        }
#pragma unroll
        for (int r = 0; r < ROWS; r++) {
            int c = warp + 4 * r;
            float4 w = c_Wp[wbase + c * Cin + ic];
#pragma unroll
            for (int i = 0; i < NI; i++) {
                acc[r][i] = fmaf(w.x, x0[i], acc[r][i]);
                acc[r][i] = fmaf(w.y, x1[i], acc[r][i]);
                acc[r][i] = fmaf(w.z, x2[i], acc[r][i]);
            }
        }
    }

    float gv[NI], bv[NI];
#pragma unroll
    for (int i = 0; i < NI; i++) {
        int l = lane + 32 * i;
        gv[i] = (l < Lout) ? __ldg(gam + l) : 0.f;
        bv[i] = (l < Lout) ? __ldg(bet + l) : 0.f;
    }
    const float invL = 1.0f / (float)Lout;

#pragma unroll
    for (int r = 0; r < ROWS; r++) {
        int c = warp + 4 * r;
        float s = 0.f;
#pragma unroll
        for (int i = 0; i < NI; i++) { int l = lane + 32 * i; if (l < Lout) s += acc[r][i]; }
#pragma unroll
        for (int o = 16; o; o >>= 1) s += __shfl_xor_sync(0xffffffffu, s, o);
        float mu = s * invL;

        float s2 = 0.f;
#pragma unroll
        for (int i = 0; i < NI; i++) {
            int l = lane + 32 * i;
            if (l < Lout) { float d = acc[r][i] - mu; s2 = fmaf(d, d, s2); }
        }
#pragma unroll
        for (int o = 16; o; o >>= 1) s2 += __shfl_xor_sync(0xffffffffu, s2, o);
        float inv = rsqrtf(fmaf(s2, invL, 1e-5f));

#pragma unroll
        for (int i = 0; i < NI; i++) {
            int l = lane + 32 * i;
            if (l < Lout) {
                float val = (acc[r][i] - mu) * inv;
                out[c * Sout + l] = fmaxf(fmaf(val, gv[i], bv[i]), 0.f);
            }
        }
    }
}

__global__ void __launch_bounds__(NT)
spectral_kernel(const float* __restrict__ x, float* __restrict__ out,
                const float* __restrict__ ln1w, const float* __restrict__ ln1b,
                const float* __restrict__ ln2w, const float* __restrict__ ln2b,
                const float* __restrict__ ln3w, const float* __restrict__ ln3b,
                const float* __restrict__ ln4w, const float* __restrict__ ln4b)
{
    __shared__ __align__(16) float  raw[2 * 144];
    __shared__ __align__(16) float  vin[2 * 144];
    __shared__ __align__(16) float2 twl[144];
    __shared__ __align__(16) float  bufA[16 * 72];
    __shared__ __align__(16) float  bufB[28 * 36];

    int tid  = threadIdx.x;
    int lane = tid & 31, warp = tid >> 5;
    unsigned blk = blockIdx.x;
    int b      = (int)(blk >> 5);
    int rem    = (int)(blk & 31);
    int stream = rem >> 3;       // 0=cr, 1=cc, 2=cr_fft, 3=cc_fft
    int m      = rem & 7;        // output spatial slot s%8
    bool isfft = (stream >= 2);
    bool isrow = (stream == 0 || stream == 2);

    const float* xb = x + (size_t)b * (CHN * 64);

    // ---- gather the (2,143) sample into smem ----
    // cr/cr_fft: sample m -> h = 3 + (m>>2), channels are w = 2*(m&3) + c
    // cc/cc_fft: sample m -> h = m,          channels are w = 3 + c
    int base = isrow ? ((3 + (m >> 2)) * 8 + (m & 3) * 2)
                     : (m * 8 + 3);
    for (int t = tid; t < 286; t += NT) {
        int c = (t >= 143); int ch = t - 143 * c;
        raw[c * 144 + ch] = __ldg(xb + ch * 64 + base + c);
    }
    if (isfft) {
        for (int t = tid; t < 143; t += NT) twl[t] = g_tw[t];
    }
    __syncthreads();

    // ---- DFT magnitude (fft streams only; block-uniform branch) ----
    if (isfft) {
        dft_one(tid, raw, twl, vin);
        if (tid < 16) dft_one(tid + 128, raw, twl, vin);
        __syncthreads();
    }

    const float* cin = isfft ? vin : raw;

    if (!isfft) {
        convBlock<2, 16, 144, 71, 3>(cin,  bufA, 72, 0,    ln1w, ln1b, warp, lane);
        __syncthreads();
        convBlock<16, 28, 72, 35, 2>(bufA, bufB, 36, 32,   ln2w, ln2b, warp, lane);
        __syncthreads();
        convBlock<28, 28, 36, 17, 1>(bufB, bufA, 18, 480,  ln3w, ln3b, warp, lane);
        __syncthreads();
        convBlock<28, 28, 18,  8, 1>(bufA, bufB,  8, 1264, ln4w, ln4b, warp, lane);
        __syncthreads();
        int cbase = stream * 28;                       // 0 or 28
        size_t obase = (size_t)b * 4096 + (size_t)cbase * 64 + (size_t)m * 8;
        for (int t = tid; t < 224; t += NT) {
            int c = t >> 3, j = t & 7;
            out[obase + (size_t)c * 64 + j] = bufB[t];
        }
    } else {
        convBlock<2, 4, 144, 71, 3>(cin,  bufA, 72, 2048, ln1w, ln1b, warp, lane);
        __syncthreads();
        convBlock<4, 4, 72, 35, 2>(bufA, bufB, 36, 2056, ln2w, ln2b, warp, lane);
        __syncthreads();
        convBlock<4, 4, 36, 17, 1>(bufB, bufA, 18, 2072, ln3w, ln3b, warp, lane);
        __syncthreads();
        convBlock<4, 4, 18,  8, 1>(bufA, bufB,  8, 2088, ln4w, ln4b, warp, lane);
        __syncthreads();
        int cbase = 56 + (stream - 2) * 4;             // 56 or 60
        size_t obase = (size_t)b * 4096 + (size_t)cbase * 64 + (size_t)m * 8;
        for (int t = tid; t < 32; t += NT) {
            int c = t >> 3, j = t & 7;
            out[obase + (size_t)c * 64 + j] = bufB[t];
        }
    }
}

extern "C" void kernel_launch(void* const* d_in, const int* in_sizes, int n_in,
                              void* d_out, int out_size)
{
    const float* x   = (const float*)d_in[0];
    const float* w1  = (const float*)d_in[1];
    const float* w2  = (const float*)d_in[2];
    const float* w3  = (const float*)d_in[3];
    const float* w4  = (const float*)d_in[4];
    const float* f1  = (const float*)d_in[5];
    const float* f2  = (const float*)d_in[6];
    const float* f3  = (const float*)d_in[7];
    const float* f4  = (const float*)d_in[8];
    const float* ln1w = (const float*)d_in[9];
    const float* ln1b = (const float*)d_in[10];
    const float* ln2w = (const float*)d_in[11];
    const float* ln2b = (const float*)d_in[12];
    const float* ln3w = (const float*)d_in[13];
    const float* ln3b = (const float*)d_in[14];
    const float* ln4w = (const float*)d_in[15];
    const float* ln4b = (const float*)d_in[16];
    float* out = (float*)d_out;

    int B = in_sizes[0] / (CHN * 64);   // 4096

    init_pack<<<1, 256>>>(w1, w2, w3, w4, f1, f2, f3, f4);

    // Publish packed weights to __constant__ memory (D2D memcpy node in the
    // graph; ordered after init_pack on the same stream).
    void* stage_ptr = 0;
    cudaGetSymbolAddress(&stage_ptr, g_Wp_stage);
    cudaMemcpyToSymbolAsync(c_Wp, stage_ptr, sizeof(float4) * 2104, 0,
                            cudaMemcpyDeviceToDevice, 0);

    spectral_kernel<<<B * 32, NT>>>(x, out,
                                    ln1w, ln1b, ln2w, ln2b,
                                    ln3w, ln3b, ln4w, ln4b);
}

// round 12
// speedup vs baseline: 12.1146x; 12.1146x over previous
#include <cuda_runtime.h>
#include <math.h>

#define CHN 143
#define NT  128

// Packed weights (float4 per (cout,cin) triple, 4th lane = 0) + twiddles.
// Layout (float4 units): W1@0(32), W2@32(448), W3@480(784), W4@1264(784),
//                        F1@2048(8), F2@2056(16), F3@2072(16), F4@2088(16)
__device__ float4 g_Wp[2104];
__device__ float2 g_tw[144];

__device__ __forceinline__ void copy3(float* dst, const float* src) {
    dst[0] = src[0]; dst[1] = src[1]; dst[2] = src[2]; dst[3] = 0.f;
}

__global__ void init_pack(const float* w1, const float* w2, const float* w3, const float* w4,
                          const float* f1, const float* f2, const float* f3, const float* f4)
{
    int tid = threadIdx.x;
    float* g = (float*)g_Wp;
    for (int e = tid; e < 32;  e += 256) copy3(g + (0    + e) * 4, w1 + e * 3);
    for (int e = tid; e < 448; e += 256) copy3(g + (32   + e) * 4, w2 + e * 3);
    for (int e = tid; e < 784; e += 256) copy3(g + (480  + e) * 4, w3 + e * 3);
    for (int e = tid; e < 784; e += 256) copy3(g + (1264 + e) * 4, w4 + e * 3);
    for (int e = tid; e < 8;   e += 256) copy3(g + (2048 + e) * 4, f1 + e * 3);
    for (int e = tid; e < 16;  e += 256) copy3(g + (2056 + e) * 4, f2 + e * 3);
    for (int e = tid; e < 16;  e += 256) copy3(g + (2072 + e) * 4, f3 + e * 3);
    for (int e = tid; e < 16;  e += 256) copy3(g + (2088 + e) * 4, f4 + e * 3);
    if (tid < 143) {
        double a = -2.0 * 3.14159265358979323846 * (double)tid / 143.0;
        g_tw[tid] = make_float2((float)cos(a), (float)sin(a));
    }
}

// One DFT bin task: u in [0,144) -> (vector c, bin k). Writes |X[k]| and |X[143-k]|.
__device__ __forceinline__ void dft_one(int u, const float* raw, const float2* twl, float* vin)
{
    int c = (u >= 72) ? 1 : 0;
    int k = u - 72 * c;
    const float* v = raw + c * 144;
    float re = 0.f, im = 0.f;
    unsigned mc = 0;
#pragma unroll 13
    for (int n = 0; n < 143; n++) {
        float2 w = twl[mc];
        float val = v[n];
        re = fmaf(w.x, val, re);
        im = fmaf(w.y, val, im);
        mc += (unsigned)k;
        mc = min(mc, mc - 143u);   // conditional wrap via unsigned-min trick
    }
    float mag = sqrtf(fmaf(re, re, im * im));
    vin[c * 144 + k] = mag;
    if (k) vin[c * 144 + 143 - k] = mag;
}

// -------- per-sample conv (stage 1 only; weights tiny) --------
template<int Cin, int Cout, int Sin, int Lout, int NI>
__device__ __forceinline__ void convBlock(
    const float* __restrict__ in, float* __restrict__ out, int Sout,
    const float4* __restrict__ Wp,
    const float* __restrict__ gam, const float* __restrict__ bet,
    int warp, int lane)
{
    constexpr int ROWS = Cout / 4;
    float acc[ROWS][NI];
#pragma unroll
    for (int r = 0; r < ROWS; r++)
#pragma unroll
        for (int i = 0; i < NI; i++) acc[r][i] = 0.f;

#pragma unroll
    for (int ic = 0; ic < Cin; ic++) {
        const float* row = in + ic * Sin;
        float x0[NI], x1[NI], x2[NI];
#pragma unroll
        for (int i = 0; i < NI; i++) {
            int l = lane + 32 * i;
            if (l < Lout) {
                float2 p = *(const float2*)(row + 2 * l);
                x0[i] = p.x; x1[i] = p.y; x2[i] = row[2 * l + 2];
            } else { x0[i] = 0.f; x1[i] = 0.f; x2[i] = 0.f; }
        }
#pragma unroll
        for (int r = 0; r < ROWS; r++) {
            int c = warp + 4 * r;
            float4 w = __ldg(Wp + c * Cin + ic);
#pragma unroll
            for (int i = 0; i < NI; i++) {
                acc[r][i] = fmaf(w.x, x0[i], acc[r][i]);
                acc[r][i] = fmaf(w.y, x1[i], acc[r][i]);
                acc[r][i] = fmaf(w.z, x2[i], acc[r][i]);
            }
        }
    }

    float gv[NI], bv[NI];
#pragma unroll
    for (int i = 0; i < NI; i++) {
        int l = lane + 32 * i;
        gv[i] = (l < Lout) ? __ldg(gam + l) : 0.f;
        bv[i] = (l < Lout) ? __ldg(bet + l) : 0.f;
    }
    const float invL = 1.0f / (float)Lout;

#pragma unroll
    for (int r = 0; r < ROWS; r++) {
        int c = warp + 4 * r;
        float s = 0.f;
#pragma unroll
        for (int i = 0; i < NI; i++) { int l = lane + 32 * i; if (l < Lout) s += acc[r][i]; }
#pragma unroll
        for (int o = 16; o; o >>= 1) s += __shfl_xor_sync(0xffffffffu, s, o);
        float mu = s * invL;

        float s2 = 0.f;
#pragma unroll
        for (int i = 0; i < NI; i++) {
            int l = lane + 32 * i;
            if (l < Lout) { float d = acc[r][i] - mu; s2 = fmaf(d, d, s2); }
        }
#pragma unroll
        for (int o = 16; o; o >>= 1) s2 += __shfl_xor_sync(0xffffffffu, s2, o);
        float inv = rsqrtf(fmaf(s2, invL, 1e-5f));

#pragma unroll
        for (int i = 0; i < NI; i++) {
            int l = lane + 32 * i;
            if (l < Lout) {
                float val = (acc[r][i] - mu) * inv;
                out[c * Sout + l] = fmaxf(fmaf(val, gv[i], bv[i]), 0.f);
            }
        }
    }
}

// -------- sample-batched conv (stages 2-4): one weight load feeds M samples --------
template<int Cin, int Cout, int Sin, int Lout, int NI, int M>
__device__ __forceinline__ void convBatch(
    const float* __restrict__ in, int inStride,
    float* __restrict__ out, int Sout, int outStride,
    const float4* __restrict__ Wp,
    const float* __restrict__ gam, const float* __restrict__ bet,
    int warp, int lane)
{
    constexpr int ROWS = Cout / 4;
    float acc[ROWS][M][NI];
#pragma unroll
    for (int r = 0; r < ROWS; r++)
#pragma unroll
        for (int m = 0; m < M; m++)
#pragma unroll
            for (int i = 0; i < NI; i++) acc[r][m][i] = 0.f;

#pragma unroll 2
    for (int ic = 0; ic < Cin; ic++) {
        float x0[M][NI], x1[M][NI], x2[M][NI];
#pragma unroll
        for (int m = 0; m < M; m++) {
            const float* row = in + m * inStride + ic * Sin;
#pragma unroll
            for (int i = 0; i < NI; i++) {
                int l = lane + 32 * i;
                if (l < Lout) {
                    float2 p = *(const float2*)(row + 2 * l);
                    x0[m][i] = p.x; x1[m][i] = p.y; x2[m][i] = row[2 * l + 2];
                } else { x0[m][i] = 0.f; x1[m][i] = 0.f; x2[m][i] = 0.f; }
            }
        }
#pragma unroll
        for (int r = 0; r < ROWS; r++) {
            int c = warp + 4 * r;
            float4 w = __ldg(Wp + c * Cin + ic);     // one load -> 3*NI*M FMAs
#pragma unroll
            for (int m = 0; m < M; m++)
#pragma unroll
                for (int i = 0; i < NI; i++) {
                    acc[r][m][i] = fmaf(w.x, x0[m][i], acc[r][m][i]);
                    acc[r][m][i] = fmaf(w.y, x1[m][i], acc[r][m][i]);
                    acc[r][m][i] = fmaf(w.z, x2[m][i], acc[r][m][i]);
                }
        }
    }

    float gv[NI], bv[NI];
#pragma unroll
    for (int i = 0; i < NI; i++) {
        int l = lane + 32 * i;
        gv[i] = (l < Lout) ? __ldg(gam + l) : 0.f;
        bv[i] = (l < Lout) ? __ldg(bet + l) : 0.f;
    }
    const float invL = 1.0f / (float)Lout;

#pragma unroll
    for (int r = 0; r < ROWS; r++) {
        int c = warp + 4 * r;
#pragma unroll
        for (int m = 0; m < M; m++) {
            float s = 0.f;
#pragma unroll
            for (int i = 0; i < NI; i++) { int l = lane + 32 * i; if (l < Lout) s += acc[r][m][i]; }
#pragma unroll
            for (int o = 16; o; o >>= 1) s += __shfl_xor_sync(0xffffffffu, s, o);
            float mu = s * invL;

            float s2 = 0.f;
#pragma unroll
            for (int i = 0; i < NI; i++) {
                int l = lane + 32 * i;
                if (l < Lout) { float d = acc[r][m][i] - mu; s2 = fmaf(d, d, s2); }
            }
#pragma unroll
            for (int o = 16; o; o >>= 1) s2 += __shfl_xor_sync(0xffffffffu, s2, o);
            float inv = rsqrtf(fmaf(s2, invL, 1e-5f));

#pragma unroll
            for (int i = 0; i < NI; i++) {
                int l = lane + 32 * i;
                if (l < Lout) {
                    float val = (acc[r][m][i] - mu) * inv;
                    out[m * outStride + c * Sout + l] = fmaxf(fmaf(val, gv[i], bv[i]), 0.f);
                }
            }
        }
    }
}

// Block = (b, stream, m-half): processes M=4 samples.
#define MB 4
#define RAW_STRIDE 288
#define A_STRIDE   1152   // 16*72
#define B_STRIDE   1008   // 28*36
#define C_STRIDE   504    // 28*18
#define D_STRIDE   224    // 28*8

__global__ void __launch_bounds__(NT)
spectral_kernel(const float* __restrict__ x, float* __restrict__ out,
                const float* __restrict__ ln1w, const float* __restrict__ ln1b,
                const float* __restrict__ ln2w, const float* __restrict__ ln2b,
                const float* __restrict__ ln3w, const float* __restrict__ ln3b,
                const float* __restrict__ ln4w, const float* __restrict__ ln4b)
{
    __shared__ __align__(16) float  raw[MB * RAW_STRIDE];
    __shared__ __align__(16) float  vin[MB * RAW_STRIDE];
    __shared__ __align__(16) float2 twl[144];
    __shared__ __align__(16) float  bufA[MB * A_STRIDE];
    __shared__ __align__(16) float  bufB[MB * B_STRIDE];

    int tid  = threadIdx.x;
    int lane = tid & 31, warp = tid >> 5;
    unsigned blk = blockIdx.x;
    int b      = (int)(blk >> 3);
    int rem    = (int)(blk & 7);
    int stream = rem >> 1;         // 0=cr, 1=cc, 2=cr_fft, 3=cc_fft
    int mbase  = (rem & 1) * MB;   // 0 or 4
    bool isfft = (stream >= 2);
    bool isrow = (stream == 0 || stream == 2);

    const float* xb = x + (size_t)b * (CHN * 64);

    // ---- gather MB (2,143) samples into smem ----
    // cr/cr_fft: sample m -> h = 3 + (m>>2), channels are w = 2*(m&3) + c
    // cc/cc_fft: sample m -> h = m,          channels are w = 3 + c
    for (int t = tid; t < MB * 286; t += NT) {
        int s = t / 286; int q = t - s * 286;
        int c = (q >= 143); int ch = q - 143 * c;
        int m = mbase + s;
        int base = isrow ? ((3 + (m >> 2)) * 8 + (m & 3) * 2)
                         : (m * 8 + 3);
        raw[s * RAW_STRIDE + c * 144 + ch] = __ldg(xb + ch * 64 + base + c);
    }
    if (isfft) {
        for (int t = tid; t < 143; t += NT) twl[t] = g_tw[t];
    }
    __syncthreads();

    // ---- DFT magnitude (fft streams only) ----
    if (isfft) {
        for (int t = tid; t < MB * 144; t += NT) {
            int s = t / 144; int u = t - s * 144;
            dft_one(u, raw + s * RAW_STRIDE, twl, vin + s * RAW_STRIDE);
        }
        __syncthreads();
    }

    const float* cin = isfft ? vin : raw;

    if (!isfft) {
        // stage 1 per-sample (weights tiny)
#pragma unroll
        for (int s = 0; s < MB; s++)
            convBlock<2, 16, 144, 71, 3>(cin + s * RAW_STRIDE, bufA + s * A_STRIDE, 72,
                                         g_Wp + 0, ln1w, ln1b, warp, lane);
        __syncthreads();
        convBatch<16, 28, 72, 35, 2, MB>(bufA, A_STRIDE, bufB, 36, B_STRIDE,
                                         g_Wp + 32,   ln2w, ln2b, warp, lane);
        __syncthreads();
        convBatch<28, 28, 36, 17, 1, MB>(bufB, B_STRIDE, bufA, 18, C_STRIDE,
                                         g_Wp + 480,  ln3w, ln3b, warp, lane);
        __syncthreads();
        convBatch<28, 28, 18,  8, 1, MB>(bufA, C_STRIDE, bufB, 8, D_STRIDE,
                                         g_Wp + 1264, ln4w, ln4b, warp, lane);
        __syncthreads();
        int cbase = stream * 28;                       // 0 or 28
        size_t obase = (size_t)b * 4096 + (size_t)cbase * 64;
        for (int t = tid; t < MB * 224; t += NT) {
            int s = t / 224; int q = t - s * 224;
            int c = q >> 3, j = q & 7;
            out[obase + (size_t)c * 64 + (size_t)(mbase + s) * 8 + j] = bufB[s * D_STRIDE + q];
        }
    } else {
#pragma unroll
        for (int s = 0; s < MB; s++)
            convBlock<2, 4, 144, 71, 3>(cin + s * RAW_STRIDE, bufA + s * A_STRIDE, 72,
                                        g_Wp + 2048, ln1w, ln1b, warp, lane);
        __syncthreads();
        convBatch<4, 4, 72, 35, 2, MB>(bufA, A_STRIDE, bufB, 36, B_STRIDE,
                                       g_Wp + 2056, ln2w, ln2b, warp, lane);
        __syncthreads();
        convBatch<4, 4, 36, 17, 1, MB>(bufB, B_STRIDE, bufA, 18, C_STRIDE,
                                       g_Wp + 2072, ln3w, ln3b, warp, lane);
        __syncthreads();
        convBatch<4, 4, 18,  8, 1, MB>(bufA, C_STRIDE, bufB, 8, D_STRIDE,
                                       g_Wp + 2088, ln4w, ln4b, warp, lane);
        __syncthreads();
        int cbase = 56 + (stream - 2) * 4;             // 56 or 60
        size_t obase = (size_t)b * 4096 + (size_t)cbase * 64;
        for (int t = tid; t < MB * 32; t += NT) {
            int s = t >> 5; int q = t & 31;
            int c = q >> 3, j = q & 7;
            out[obase + (size_t)c * 64 + (size_t)(mbase + s) * 8 + j] = bufB[s * D_STRIDE + c * 8 + j];
        }
    }
}

extern "C" void kernel_launch(void* const* d_in, const int* in_sizes, int n_in,
                              void* d_out, int out_size)
{
    const float* x   = (const float*)d_in[0];
    const float* w1  = (const float*)d_in[1];
    const float* w2  = (const float*)d_in[2];
    const float* w3  = (const float*)d_in[3];
    const float* w4  = (const float*)d_in[4];
    const float* f1  = (const float*)d_in[5];
    const float* f2  = (const float*)d_in[6];
    const float* f3  = (const float*)d_in[7];
    const float* f4  = (const float*)d_in[8];
    const float* ln1w = (const float*)d_in[9];
    const float* ln1b = (const float*)d_in[10];
    const float* ln2w = (const float*)d_in[11];
    const float* ln2b = (const float*)d_in[12];
    const float* ln3w = (const float*)d_in[13];
    const float* ln3b = (const float*)d_in[14];
    const float* ln4w = (const float*)d_in[15];
    const float* ln4b = (const float*)d_in[16];
    float* out = (float*)d_out;

    int B = in_sizes[0] / (CHN * 64);   // 4096

    init_pack<<<1, 256>>>(w1, w2, w3, w4, f1, f2, f3, f4);
    spectral_kernel<<<B * 8, NT>>>(x, out,
                                   ln1w, ln1b, ln2w, ln2b,
                                   ln3w, ln3b, ln4w, ln4b);
}